// round 2
// baseline (speedup 1.0000x reference)
#include <cuda_runtime.h>
#include <cstdint>

// Problem constants (match reference)
#define N_EVENTS   16
#define N_SAMPLES  32768
#define STEP_SIZE  256
#define BATCH      64

// Each thread produces 4 consecutive output samples (float4).
// 256 threads/block -> 1024 samples per block -> 32 blocks per batch row.
#define THREADS    256
#define SAMPLES_PER_BLOCK (THREADS * 4)

__global__ __launch_bounds__(THREADS)
void render_gather_kernel(const float* __restrict__ x,
                          const int* __restrict__ indices,
                          float* __restrict__ out) {
    const int b = blockIdx.y;
    const int j = (blockIdx.x * THREADS + threadIdx.x) * 4;  // output sample base

    // Broadcast the 16 event start-times for this batch into shared memory.
    __shared__ int t_start[N_EVENTS];
    if (threadIdx.x < N_EVENTS) {
        t_start[threadIdx.x] = indices[b * N_EVENTS + threadIdx.x] * STEP_SIZE;
    }
    __syncthreads();

    const float* xb = x + (size_t)b * N_EVENTS * N_SAMPLES;

    float4 acc = make_float4(0.f, 0.f, 0.f, 0.f);
    #pragma unroll
    for (int e = 0; e < N_EVENTS; e++) {
        const int k = j - t_start[e];
        // t_start multiple of 256, j multiple of 4 -> k multiple of 4 (16B aligned).
        // k < N_SAMPLES always holds since j < N_SAMPLES and t_start >= 0.
        if (k >= 0) {
            const float4 v = *reinterpret_cast<const float4*>(
                xb + (size_t)e * N_SAMPLES + k);
            acc.x += v.x; acc.y += v.y; acc.z += v.z; acc.w += v.w;
        }
    }

    *reinterpret_cast<float4*>(out + (size_t)b * N_SAMPLES + j) = acc;
}

extern "C" void kernel_launch(void* const* d_in, const int* in_sizes, int n_in,
                              void* d_out, int out_size) {
    const float* x = (const float*)d_in[0];          // (64, 16, 32768) f32
    const int* indices = (const int*)d_in[1];        // (64, 16) int32 (JAX x64 disabled)
    float* out = (float*)d_out;                      // (64, 1, 32768) f32

    dim3 grid(N_SAMPLES / SAMPLES_PER_BLOCK, BATCH); // (32, 64)
    render_gather_kernel<<<grid, THREADS>>>(x, indices, out);
}